// round 6
// baseline (speedup 1.0000x reference)
#include <cuda_runtime.h>
#include <cstdint>

#define DD    32          // embedding dim D
#define MM    32          // memories per hop
#define LEAKY 0.2f
#define CAP   1024        // bucket capacity per relation (mean ~655 @uniform)
#define CPR   (CAP / 8)   // chunk-blocks per relation (8 slots each)
#define OB    32          // overflow blocks

// scratch
__device__ float g_Rh[131072 * 32];     // Rh[slot][d]
__device__ int   g_slots[1 << 20];      // REL*CAP slot ids (REL<=1024)
__device__ int   g_cnt[1024];
__device__ int   g_ov[131072];          // overflow can hold EVERY slot (safe)
__device__ int   g_ovcnt;

__device__ __forceinline__ float warpSum(float v) {
    #pragma unroll
    for (int off = 16; off; off >>= 1) v += __shfl_xor_sync(0xffffffffu, v, off);
    return v;
}
__device__ __forceinline__ float warpMax(float v) {
    #pragma unroll
    for (int off = 16; off; off >>= 1) v = fmaxf(v, __shfl_xor_sync(0xffffffffu, v, off));
    return v;
}
__device__ __forceinline__ void cp16(uint32_t saddr, const void* gaddr) {
    asm volatile("cp.async.cg.shared.global [%0], [%1], 16;" :: "r"(saddr), "l"(gaddr));
}

// ---------------------------------------------------------------------------
__global__ void zero_kernel(int REL) {
    for (int i = threadIdx.x; i < REL; i += blockDim.x) g_cnt[i] = 0;
    if (threadIdx.x == 0) g_ovcnt = 0;
}
__global__ void fill_kernel(const int* __restrict__ mr, int HBM) {
    int s = blockIdx.x * blockDim.x + threadIdx.x;
    if (s >= HBM) return;
    int r = __ldg(&mr[s]);
    int idx = atomicAdd(&g_cnt[r], 1);
    if (idx < CAP) g_slots[r * CAP + idx] = s;
    else           g_ov[atomicAdd(&g_ovcnt, 1)] = s;
}

// ---------------------------------------------------------------------------
// MEGA kernel, blockIdx ranges (r-work first = long pole):
//  [0, REL*CPR)   : bucketed r-gather. Block loads its relation's 4KB row into
//                   smem ONCE, then 8 warps each serve one slot: replicate row
//                   to out_r + fused Rh. rel L2 read traffic drops 8x.
//  [.., +OB)      : overflow slots (direct per-slot path; empty @uniform)
//  next HB blocks : h_all / t_all gather
//  next CB blocks : uEmbed + iEmbed copy
// ---------------------------------------------------------------------------
__global__ void __launch_bounds__(256) mega_kernel(
        const int*    __restrict__ mh,
        const int*    __restrict__ mr,
        const int*    __restrict__ mt,
        const float4* __restrict__ uE4,
        const float4* __restrict__ iE4,
        const float4* __restrict__ ent4,
        const float4* __restrict__ rel4,
        float4* __restrict__ out_u4,
        float4* __restrict__ out_h4,
        float4* __restrict__ out_t4,
        float4* __restrict__ out_r4,
        int HBM, int REL, int HB, int Ue4, int Ie4) {
    __shared__ float sR[DD * DD];               // 4KB: one relation row
    const int RMAIN = REL * CPR;
    int blk = blockIdx.x;
    const float* ent = (const float*)ent4;

    if (blk < RMAIN) {
        int r = blk / CPR;
        int base = (blk - r * CPR) * 8;
        int cnt = min(g_cnt[r], CAP);
        if (base >= cnt) return;

        ((float4*)sR)[threadIdx.x] = __ldg(&rel4[(size_t)r * 256 + threadIdx.x]);
        __syncthreads();

        int warp = threadIdx.x >> 5, lane = threadIdx.x & 31;
        int k = base + warp;
        if (k >= cnt) return;
        int slot = g_slots[r * CAP + k];

        int e = __ldg(&mh[slot]);
        float hval = __ldg(&ent[(size_t)e * DD + lane]);

        const float4* s4 = (const float4*)sR;
        float4* dst = out_r4 + (size_t)slot * 256;
        #pragma unroll
        for (int j = 0; j < 8; j++)
            __stcs(&dst[j * 32 + lane], s4[j * 32 + lane]);

        float acc = 0.f;
        #pragma unroll
        for (int i = 0; i < DD; i++) {
            int ee = (i + lane) & (DD - 1);     // conflict-free rotation
            acc = fmaf(sR[lane * DD + ee],
                       __shfl_sync(0xffffffffu, hval, ee), acc);
        }
        g_Rh[(size_t)slot * DD + lane] = acc;
    } else if (blk < RMAIN + OB) {
        // overflow: direct per-slot path (R3 style), normally zero work
        int nov = g_ovcnt;
        int warp = threadIdx.x >> 5, lane = threadIdx.x & 31;
        for (int k = (blk - RMAIN) * 8 + warp; k < nov; k += OB * 8) {
            int slot = g_ov[k];
            int r = __ldg(&mr[slot]);
            const float4* src = rel4 + (size_t)r * 256;
            float4* dst = out_r4 + (size_t)slot * 256;
            float4 v[8];
            #pragma unroll
            for (int j = 0; j < 8; j++) v[j] = __ldg(&src[j * 32 + lane]);
            int e = __ldg(&mh[slot]);
            float hval = __ldg(&ent[(size_t)e * DD + lane]);
            #pragma unroll
            for (int j = 0; j < 8; j++) __stcs(&dst[j * 32 + lane], v[j]);
            // Rh via shfl-transpose of v (row lane of R held across lanes):
            // fall back to direct global reads for simplicity (rare path)
            const float* srcf = (const float*)src;
            float acc = 0.f;
            for (int i = 0; i < DD; i++)
                acc = fmaf(__ldg(&srcf[lane * DD + i]),
                           __shfl_sync(0xffffffffu, hval, i), acc);
            g_Rh[(size_t)slot * DD + lane] = acc;
        }
    } else if (blk < RMAIN + OB + HB) {
        // ---- h_all / t_all gather ----
        int tid = (blk - RMAIN - OB) * 256 + threadIdx.x;
        int N = HBM * 8;                  // 8 float4 per 32-float row
        if (tid < N) {
            int slot = tid >> 3, j = tid & 7;
            int e = __ldg(&mh[slot]);
            __stcs(&out_h4[slot * 8 + j], __ldg(&ent4[(size_t)e * 8 + j]));
        } else if (tid < 2 * N) {
            int t2 = tid - N;
            int slot = t2 >> 3, j = t2 & 7;
            int e = __ldg(&mt[slot]);
            float4 v = __ldg(&ent4[(size_t)e * 8 + j]);
            v.x = v.x > 0.f ? v.x : LEAKY * v.x;
            v.y = v.y > 0.f ? v.y : LEAKY * v.y;
            v.z = v.z > 0.f ? v.z : LEAKY * v.z;
            v.w = v.w > 0.f ? v.w : LEAKY * v.w;
            out_t4[slot * 8 + j] = v;     // re-read by ripple: keep cacheable
        }
    } else {
        // ---- uEmbed + iEmbed copy ----
        int j = (blk - RMAIN - OB - HB) * 256 + threadIdx.x;
        if (j < Ue4)
            __stcs(&out_u4[j], __ldg(&uE4[j]));
        else if (j < Ue4 + Ie4)
            __stcs(&out_u4[j], __ldg(&iE4[j - Ue4]));
    }
}

// ---------------------------------------------------------------------------
// Hop loop: one warp per batch row b; 2 warps/block. Both hops' Rh and t
// tiles prefetched into smem via cp.async, latency hidden behind the
// duplicate scan. Compute is then pure smem FMA.
// ---------------------------------------------------------------------------
__global__ void __launch_bounds__(64) ripple_kernel(
        const int*   __restrict__ pos,
        const float* __restrict__ iE,
        const float* __restrict__ t_all,
        const float* __restrict__ W,
        float* __restrict__ out_i,
        int B, int nhop) {
    __shared__ float sW[DD * DD];
    __shared__ float sRh[2][2][MM * DD];   // [warp][hop][m*D+d] 16KB
    __shared__ float sT [2][2][MM * DD];   // 16KB
    __shared__ float sIt[2][DD];

    int warp = threadIdx.x >> 5, lane = threadIdx.x & 31;
    int b = blockIdx.x * 2 + warp;
    bool active = (b < B);
    int p = active ? __ldg(&pos[b]) : 0;
    int npre = nhop < 2 ? nhop : 2;

    // issue all prefetches first (32 cp.asyncs per lane)
    if (active) {
        for (int h = 0; h < npre; h++) {
            const float4* Rh4 = (const float4*)(g_Rh + (size_t)(h * B + b) * MM * DD);
            const float4* T4  = (const float4*)(t_all + (size_t)(h * B + b) * MM * DD);
            uint32_t sa = (uint32_t)__cvta_generic_to_shared(&sRh[warp][h][0]);
            uint32_t sb = (uint32_t)__cvta_generic_to_shared(&sT[warp][h][0]);
            #pragma unroll
            for (int j = 0; j < 8; j++) {
                cp16(sa + (j * 32 + lane) * 16, &Rh4[j * 32 + lane]);
                cp16(sb + (j * 32 + lane) * 16, &T4[j * 32 + lane]);
            }
        }
    }
    asm volatile("cp.async.commit_group;");

    for (int i = threadIdx.x; i < DD * DD; i += 64) sW[i] = __ldg(&W[i]);

    float item = active ? __ldg(&iE[(size_t)p * DD + lane]) : 0.f;

    // last-wins duplicate scan overlaps the async loads
    bool dup = false;
    if (active)
        for (int j = b + 1 + lane; j < B; j += 32) dup |= (__ldg(&pos[j]) == p);
    dup = __any_sync(0xffffffffu, dup);

    __syncthreads();                       // sW ready (all 64 threads alive)
    if (!active || dup) return;

    asm volatile("cp.async.wait_group 0;" ::: "memory");
    __syncwarp();

    float* myIt = sIt[warp];
    for (int hop = 0; hop < nhop; hop++) {
        float* myRh = sRh[warp][hop & 1];
        float* myT  = sT [warp][hop & 1];
        if (hop >= 2) {                    // generic fallback (unused @nhop=2)
            const float4* Rh4 = (const float4*)(g_Rh + (size_t)(hop * B + b) * MM * DD);
            const float4* T4  = (const float4*)(t_all + (size_t)(hop * B + b) * MM * DD);
            #pragma unroll
            for (int j = 0; j < 8; j++) {
                ((float4*)myRh)[j * 32 + lane] = __ldg(&Rh4[j * 32 + lane]);
                ((float4*)myT )[j * 32 + lane] = __ldg(&T4[j * 32 + lane]);
            }
            __syncwarp();
        }
        myIt[lane] = item;
        __syncwarp();
        // logit[m] on lane m: independent FMAs, conflict-free rotation
        float logit = 0.f;
        #pragma unroll
        for (int i = 0; i < DD; i++) {
            int ee = (i + lane) & (DD - 1);
            logit = fmaf(myRh[lane * DD + ee], myIt[ee], logit);
        }
        float mx = warpMax(logit);
        float ex = expf(logit - mx);
        float prob = ex / warpSum(ex);
        // o[d] = sum_m prob[m] * t[m][d]  (smem, conflict-free)
        float o = 0.f;
        #pragma unroll
        for (int m = 0; m < MM; m++) {
            float pm = __shfl_sync(0xffffffffu, prob, m);
            o = fmaf(pm, myT[m * DD + lane], o);
        }
        __syncwarp();
        myIt[lane] = item + o;
        __syncwarp();
        float ni = 0.f;
        #pragma unroll
        for (int e = 0; e < DD; e++) {
            int ee = (e + lane) & (DD - 1);
            ni = fmaf(myIt[ee], sW[lane * DD + ee], ni);
        }
        item = ni;
        __syncwarp();
    }
    out_i[(size_t)p * DD + lane] = item;
}

// ---------------------------------------------------------------------------
extern "C" void kernel_launch(void* const* d_in, const int* in_sizes, int n_in,
                              void* d_out, int out_size) {
    const int*   pos = (const int*)d_in[0];
    const int*   mh  = (const int*)d_in[1];
    const int*   mr  = (const int*)d_in[2];
    const int*   mt  = (const int*)d_in[3];
    const float* uE  = (const float*)d_in[4];
    const float* iE  = (const float*)d_in[5];
    const float* ent = (const float*)d_in[6];
    const float* rel = (const float*)d_in[7];
    const float* W   = (const float*)d_in[8];
    float* out = (float*)d_out;

    const int B    = in_sizes[0];             // 2048
    const int HBM  = in_sizes[1];             // H*B*M = 131072
    const int nhop = HBM / (B * MM);          // 2
    const int REL  = in_sizes[7] / (DD * DD); // 200
    const size_t Ue = (size_t)in_sizes[4];
    const size_t Ie = (size_t)in_sizes[5];

    float* out_u = out;
    float* out_i = out_u + Ue;
    float* out_h = out_i + Ie;
    float* out_t = out_h + (size_t)HBM * DD;
    float* out_r = out_t + (size_t)HBM * DD;

    const int HB  = (2 * HBM * 8 + 255) / 256;
    const int Ue4 = (int)(Ue / 4), Ie4 = (int)(Ie / 4);
    const int CB  = (Ue4 + Ie4 + 255) / 256;
    const int RBLK = REL * CPR + OB;

    zero_kernel<<<1, 256>>>(REL);
    fill_kernel<<<(HBM + 255) / 256, 256>>>(mr, HBM);

    mega_kernel<<<RBLK + HB + CB, 256>>>(
        mh, mr, mt,
        (const float4*)uE, (const float4*)iE,
        (const float4*)ent, (const float4*)rel,
        (float4*)out_u, (float4*)out_h, (float4*)out_t, (float4*)out_r,
        HBM, REL, HB, Ue4, Ie4);

    ripple_kernel<<<(B + 1) / 2, 64>>>(pos, iE, out_t, W, out_i, B, nhop);
}

// round 7
// speedup vs baseline: 1.2661x; 1.2661x over previous
#include <cuda_runtime.h>

#define DD    32          // embedding dim D
#define MM    32          // memories per hop
#define LEAKY 0.2f

// scratch: Rh[slot*D + d], slot in [0, H*B*M)
__device__ float g_Rh[131072 * 32];

__device__ __forceinline__ float warpSum(float v) {
    #pragma unroll
    for (int off = 16; off; off >>= 1) v += __shfl_xor_sync(0xffffffffu, v, off);
    return v;
}
__device__ __forceinline__ float warpMax(float v) {
    #pragma unroll
    for (int off = 16; off; off >>= 1) v = fmaxf(v, __shfl_xor_sync(0xffffffffu, v, off));
    return v;
}

// ---------------------------------------------------------------------------
// MEGA kernel: blockIdx ranges select role.
//   [0, RB)          : r_all gather + fused Rh (warp-per-slot, 8 slots/block)
//   [RB, RB+HB)      : h_all / t_all gather (float4 granularity)
//   [RB+HB, ...)     : uEmbed + iEmbed contiguous copy (float4)
// r-blocks first: they are the long pole; the small work backfills the tail.
// 8 consecutive slots per block -> 32KB contiguous DRAM write streams.
// ---------------------------------------------------------------------------
__global__ void __launch_bounds__(256) mega_kernel(
        const int*    __restrict__ mh,
        const int*    __restrict__ mr,
        const int*    __restrict__ mt,
        const float4* __restrict__ uE4,
        const float4* __restrict__ iE4,
        const float4* __restrict__ ent4,
        const float4* __restrict__ rel4,
        float4* __restrict__ out_u4,
        float4* __restrict__ out_h4,
        float4* __restrict__ out_t4,
        float4* __restrict__ out_r4,
        int HBM, int RB, int HB, int Ue4, int Ie4) {
    __shared__ float4 sR4[8][256];        // r-blocks only (32KB)
    int blk = blockIdx.x;
    const float* ent = (const float*)ent4;

    if (blk < RB) {
        // ---- r_all gather + Rh = R@h, one warp per slot ----
        int warp = threadIdx.x >> 5, lane = threadIdx.x & 31;
        int slot = blk * 8 + warp;
        if (slot >= HBM) return;

        int r = __ldg(&mr[slot]);
        const float4* src = rel4 + (size_t)r * 256;
        float4* dst = out_r4 + (size_t)slot * 256;
        float4* s = sR4[warp];

        float4 v[8];
        #pragma unroll
        for (int k = 0; k < 8; k++)       // 8 outstanding L2 loads per lane
            v[k] = __ldg(&src[k * 32 + lane]);

        int e = __ldg(&mh[slot]);
        float hval = __ldg(&ent[(size_t)e * DD + lane]);

        #pragma unroll
        for (int k = 0; k < 8; k++) {
            __stcs(&dst[k * 32 + lane], v[k]);  // streaming: never re-read
            s[k * 32 + lane] = v[k];
        }
        __syncwarp();

        const float* sR = (const float*)s;
        float acc = 0.f;
        #pragma unroll
        for (int i = 0; i < DD; i++) {
            int ee = (i + lane) & (DD - 1);     // conflict-free rotation
            acc = fmaf(sR[lane * DD + ee],
                       __shfl_sync(0xffffffffu, hval, ee), acc);
        }
        g_Rh[(size_t)slot * DD + lane] = acc;
    } else if (blk < RB + HB) {
        // ---- h_all / t_all gather ----
        int tid = (blk - RB) * 256 + threadIdx.x;
        int N = HBM * 8;                  // 8 float4 per 32-float row
        if (tid < N) {
            int slot = tid >> 3, j = tid & 7;
            int e = __ldg(&mh[slot]);
            __stcs(&out_h4[slot * 8 + j], __ldg(&ent4[(size_t)e * 8 + j]));
        } else if (tid < 2 * N) {
            int t2 = tid - N;
            int slot = t2 >> 3, j = t2 & 7;
            int e = __ldg(&mt[slot]);
            float4 v = __ldg(&ent4[(size_t)e * 8 + j]);
            v.x = v.x > 0.f ? v.x : LEAKY * v.x;
            v.y = v.y > 0.f ? v.y : LEAKY * v.y;
            v.z = v.z > 0.f ? v.z : LEAKY * v.z;
            v.w = v.w > 0.f ? v.w : LEAKY * v.w;
            out_t4[slot * 8 + j] = v;     // re-read by ripple: keep cacheable
        }
    } else {
        // ---- uEmbed + iEmbed copy (contiguous dst, never re-read) ----
        int j = (blk - RB - HB) * 256 + threadIdx.x;
        if (j < Ue4)
            __stcs(&out_u4[j], __ldg(&uE4[j]));
        else if (j < Ue4 + Ie4)
            __stcs(&out_u4[j], __ldg(&iE4[j - Ue4]));
    }
}

// ---------------------------------------------------------------------------
// Hop loop: one warp per batch row b; 8 warps/block (R4 structure, measured
// best). Rh tile staged in smem; t tile prefetched into registers in the
// same batch -> one exposed memory wait per hop. Last-wins scatter resolved
// by inline duplicate scan over pos (L1-hot).
// ---------------------------------------------------------------------------
__global__ void __launch_bounds__(256) ripple_kernel(
        const int*   __restrict__ pos,
        const float* __restrict__ iE,
        const float* __restrict__ t_all,
        const float* __restrict__ W,
        float* __restrict__ out_i,
        int B, int nhop) {
    __shared__ float sW[DD * DD];
    __shared__ float sRh[8][DD * DD];   // 32KB: per-warp Rh tile
    __shared__ float sIt[8][DD];
    for (int i = threadIdx.x; i < DD * DD; i += blockDim.x) sW[i] = W[i];
    __syncthreads();
    int warp = threadIdx.x >> 5, lane = threadIdx.x & 31;
    int b = blockIdx.x * 8 + warp;
    if (b >= B) return;
    int p = pos[b];

    // last-wins: if any later batch element maps to the same item, we lose.
    bool dup = false;
    for (int j = b + 1 + lane; j < B; j += 32) dup |= (pos[j] == p);
    if (__any_sync(0xffffffffu, dup)) return;

    float item = iE[(size_t)p * DD + lane];
    float* myRh = sRh[warp];
    float* myIt = sIt[warp];

    for (int hop = 0; hop < nhop; hop++) {
        const float4* Rh4 = (const float4*)(g_Rh + (size_t)(hop * B + b) * MM * DD);
        const float4* T4  = (const float4*)(t_all + (size_t)(hop * B + b) * MM * DD);
        float4 tt[8];
        #pragma unroll
        for (int j = 0; j < 8; j++) {     // 16 outstanding loads, one wait
            ((float4*)myRh)[j * 32 + lane] = __ldg(&Rh4[j * 32 + lane]);
            tt[j] = __ldg(&T4[j * 32 + lane]);
        }
        myIt[lane] = item;
        __syncwarp();
        // logit[m] on lane m: independent FMAs, conflict-free rotation
        float logit = 0.f;
        #pragma unroll
        for (int i = 0; i < DD; i++) {
            int ee = (i + lane) & (DD - 1);
            logit = fmaf(myRh[lane * DD + ee], myIt[ee], logit);
        }
        // softmax across lanes
        float mx = warpMax(logit);
        float ex = expf(logit - mx);
        float prob = ex / warpSum(ex);
        // o[d] = sum_m prob[m] * t[m][d]. tt[j] holds t[row 4j+lane/8][...]:
        // element layout matches Rh: float4 index j*32+lane = floats of
        // t[(j*32+lane)/8][((j*32+lane)%8)*4 ..+3]. Reuse smem staging for
        // a clean [m][d] access instead of a register transpose.
        __syncwarp();
        #pragma unroll
        for (int j = 0; j < 8; j++)
            ((float4*)myRh)[j * 32 + lane] = tt[j];   // myRh now holds t-tile
        __syncwarp();
        float o = 0.f;
        #pragma unroll
        for (int m = 0; m < MM; m++) {
            float pm = __shfl_sync(0xffffffffu, prob, m);
            o = fmaf(pm, myRh[m * DD + lane], o);
        }
        // item = (item + o) @ W.T via smem broadcast
        __syncwarp();
        myIt[lane] = item + o;
        __syncwarp();
        float ni = 0.f;
        #pragma unroll
        for (int e = 0; e < DD; e++) {
            int ee = (e + lane) & (DD - 1);
            ni = fmaf(myIt[ee], sW[lane * DD + ee], ni);
        }
        item = ni;
        __syncwarp();
    }
    out_i[(size_t)p * DD + lane] = item;
}

// ---------------------------------------------------------------------------
extern "C" void kernel_launch(void* const* d_in, const int* in_sizes, int n_in,
                              void* d_out, int out_size) {
    const int*   pos = (const int*)d_in[0];
    const int*   mh  = (const int*)d_in[1];
    const int*   mr  = (const int*)d_in[2];
    const int*   mt  = (const int*)d_in[3];
    const float* uE  = (const float*)d_in[4];
    const float* iE  = (const float*)d_in[5];
    const float* ent = (const float*)d_in[6];
    const float* rel = (const float*)d_in[7];
    const float* W   = (const float*)d_in[8];
    float* out = (float*)d_out;

    const int B    = in_sizes[0];             // 2048
    const int HBM  = in_sizes[1];             // H*B*M = 131072
    const int nhop = HBM / (B * MM);          // 2
    const size_t Ue = (size_t)in_sizes[4];    // USER*D floats
    const size_t Ie = (size_t)in_sizes[5];    // ITEM*D floats

    float* out_u = out;
    float* out_i = out_u + Ue;
    float* out_h = out_i + Ie;
    float* out_t = out_h + (size_t)HBM * DD;
    float* out_r = out_t + (size_t)HBM * DD;

    const int RB  = (HBM + 7) / 8;                      // 16384 r-blocks
    const int HB  = (2 * HBM * 8 + 255) / 256;          // 8192 ht-blocks
    const int Ue4 = (int)(Ue / 4), Ie4 = (int)(Ie / 4);
    const int CB  = (Ue4 + Ie4 + 255) / 256;            // 6250 copy-blocks

    mega_kernel<<<RB + HB + CB, 256>>>(
        mh, mr, mt,
        (const float4*)uE, (const float4*)iE,
        (const float4*)ent, (const float4*)rel,
        (float4*)out_u, (float4*)out_h, (float4*)out_t, (float4*)out_r,
        HBM, RB, HB, Ue4, Ie4);

    ripple_kernel<<<(B + 7) / 8, 256>>>(pos, iE, out_t, W, out_i, B, nhop);
}

// round 8
// speedup vs baseline: 1.4028x; 1.1079x over previous
#include <cuda_runtime.h>

#define DD    32          // embedding dim D
#define MM    32          // memories per hop
#define LEAKY 0.2f

// scratch: Rh[slot*D + d], slot in [0, H*B*M)
__device__ float g_Rh[131072 * 32];

__device__ __forceinline__ float warpSum(float v) {
    #pragma unroll
    for (int off = 16; off; off >>= 1) v += __shfl_xor_sync(0xffffffffu, v, off);
    return v;
}
__device__ __forceinline__ float warpMax(float v) {
    #pragma unroll
    for (int off = 16; off; off >>= 1) v = fmaxf(v, __shfl_xor_sync(0xffffffffu, v, off));
    return v;
}

// ---------------------------------------------------------------------------
// MEGA kernel: blockIdx ranges select role.
//   [0, RB)          : r_all gather + fused Rh (warp-per-slot, 8 slots/block)
//   [RB, RB+HB)      : h_all / t_all gather (float4 granularity)
//   [RB+HB, ...)     : uEmbed + iEmbed contiguous copy (float4)
// ZERO shared memory -> full 228KB L1D carveout -> the 800KB rel table gets
// real L1 hits (each SM re-touches each row ~4.4x), cutting LTS read traffic.
// Rh mat-vec done entirely in registers via shuffle butterflies.
// ---------------------------------------------------------------------------
__global__ void __launch_bounds__(256) mega_kernel(
        const int*    __restrict__ mh,
        const int*    __restrict__ mr,
        const int*    __restrict__ mt,
        const float4* __restrict__ uE4,
        const float4* __restrict__ iE4,
        const float4* __restrict__ ent4,
        const float4* __restrict__ rel4,
        float4* __restrict__ out_u4,
        float4* __restrict__ out_h4,
        float4* __restrict__ out_t4,
        float4* __restrict__ out_r4,
        int HBM, int RB, int HB, int Ue4, int Ie4) {
    int blk = blockIdx.x;
    const float* ent = (const float*)ent4;
    const unsigned FULL = 0xffffffffu;

    if (blk < RB) {
        // ---- r_all gather + Rh = R@h, one warp per slot, register-only ----
        int warp = threadIdx.x >> 5, lane = threadIdx.x & 31;
        int slot = blk * 8 + warp;
        if (slot >= HBM) return;

        int r = __ldg(&mr[slot]);
        const float4* src = rel4 + (size_t)r * 256;
        float4* dst = out_r4 + (size_t)slot * 256;

        float4 v[8];
        #pragma unroll
        for (int k = 0; k < 8; k++)       // 8 outstanding loads (L1/L2)
            v[k] = __ldg(&src[k * 32 + lane]);

        int e = __ldg(&mh[slot]);
        float hval = __ldg(&ent[(size_t)e * DD + lane]);

        // h4 = h[4c..4c+3], c = lane&7  (v[k] covers R[4k+(lane>>3)][4c..4c+3])
        int c4 = (lane & 7) * 4;
        float hx = __shfl_sync(FULL, hval, c4 + 0);
        float hy = __shfl_sync(FULL, hval, c4 + 1);
        float hz = __shfl_sync(FULL, hval, c4 + 2);
        float hw = __shfl_sync(FULL, hval, c4 + 3);

        float p[8];
        #pragma unroll
        for (int k = 0; k < 8; k++) {
            __stcs(&dst[k * 32 + lane], v[k]);   // streaming write-out
            p[k] = v[k].x * hx + v[k].y * hy + v[k].z * hz + v[k].w * hw;
        }
        // reduce partials within each 8-lane group: p[k] -> full dot of
        // row (4k + lane>>3)
        #pragma unroll
        for (int k = 0; k < 8; k++) {
            p[k] += __shfl_xor_sync(FULL, p[k], 1);
            p[k] += __shfl_xor_sync(FULL, p[k], 2);
            p[k] += __shfl_xor_sync(FULL, p[k], 4);
        }
        // permutation: lane d wants row d = 4k+g (k=d>>2, g=d&3), held in
        // register p[d>>2] on lanes 8g..8g+7. Each source lane L is read by
        // exactly one dest d=4*(L&7)+(L>>3), which needs p[L&7].
        int myk = lane & 7;
        float temp = p[0];
        #pragma unroll
        for (int k = 1; k < 8; k++) if (myk == k) temp = p[k];
        float acc = __shfl_sync(FULL, temp, ((lane & 3) << 3) + (lane >> 2));
        g_Rh[(size_t)slot * DD + lane] = acc;
    } else if (blk < RB + HB) {
        // ---- h_all / t_all gather ----
        int tid = (blk - RB) * 256 + threadIdx.x;
        int N = HBM * 8;                  // 8 float4 per 32-float row
        if (tid < N) {
            int slot = tid >> 3, j = tid & 7;
            int e = __ldg(&mh[slot]);
            __stcs(&out_h4[slot * 8 + j], __ldg(&ent4[(size_t)e * 8 + j]));
        } else if (tid < 2 * N) {
            int t2 = tid - N;
            int slot = t2 >> 3, j = t2 & 7;
            int e = __ldg(&mt[slot]);
            float4 v = __ldg(&ent4[(size_t)e * 8 + j]);
            v.x = v.x > 0.f ? v.x : LEAKY * v.x;
            v.y = v.y > 0.f ? v.y : LEAKY * v.y;
            v.z = v.z > 0.f ? v.z : LEAKY * v.z;
            v.w = v.w > 0.f ? v.w : LEAKY * v.w;
            out_t4[slot * 8 + j] = v;     // re-read by ripple: keep cacheable
        }
    } else {
        // ---- uEmbed + iEmbed copy (contiguous dst, never re-read) ----
        int j = (blk - RB - HB) * 256 + threadIdx.x;
        if (j < Ue4)
            __stcs(&out_u4[j], __ldg(&uE4[j]));
        else if (j < Ue4 + Ie4)
            __stcs(&out_u4[j], __ldg(&iE4[j - Ue4]));
    }
}

// ---------------------------------------------------------------------------
// Hop loop (R4 measured-best form): one warp per batch row b, 8 warps/block.
// Rh tile staged in smem (kills SHFL dependency chains); t loaded coalesced
// from L2-hot out_t. Last-wins scatter resolved by inline duplicate scan.
// ---------------------------------------------------------------------------
__global__ void __launch_bounds__(256) ripple_kernel(
        const int*   __restrict__ pos,
        const float* __restrict__ iE,
        const float* __restrict__ t_all,
        const float* __restrict__ W,
        float* __restrict__ out_i,
        int B, int nhop) {
    __shared__ float sW[DD * DD];
    __shared__ float sRh[8][DD * DD];   // 32KB: per-warp Rh tile
    __shared__ float sIt[8][DD];
    for (int i = threadIdx.x; i < DD * DD; i += blockDim.x) sW[i] = W[i];
    __syncthreads();
    int warp = threadIdx.x >> 5, lane = threadIdx.x & 31;
    int b = blockIdx.x * 8 + warp;
    if (b >= B) return;
    int p = pos[b];

    // last-wins: if any later batch element maps to the same item, we lose.
    bool dup = false;
    for (int j = b + 1 + lane; j < B; j += 32) dup |= (pos[j] == p);
    if (__any_sync(0xffffffffu, dup)) return;

    float item = iE[(size_t)p * DD + lane];
    float* myRh = sRh[warp];
    float* myIt = sIt[warp];

    for (int hop = 0; hop < nhop; hop++) {
        const float4* Rh4 = (const float4*)(g_Rh + (size_t)(hop * B + b) * MM * DD);
        #pragma unroll
        for (int j = 0; j < 8; j++)
            ((float4*)myRh)[j * 32 + lane] = __ldg(&Rh4[j * 32 + lane]);
        myIt[lane] = item;
        __syncwarp();
        // logit[m] on lane m: 32 independent FMAs, conflict-free rotation
        float logit = 0.f;
        #pragma unroll
        for (int i = 0; i < DD; i++) {
            int ee = (i + lane) & (DD - 1);
            logit = fmaf(myRh[lane * DD + ee], myIt[ee], logit);
        }
        // softmax across lanes
        float mx = warpMax(logit);
        float ex = expf(logit - mx);
        float prob = ex / warpSum(ex);
        // o[d] = sum_m prob[m] * t[m][d]  (coalesced L2-hot loads)
        const float* tb = t_all + (size_t)(hop * B + b) * MM * DD;
        float o = 0.f;
        #pragma unroll
        for (int m = 0; m < MM; m++) {
            float pm = __shfl_sync(0xffffffffu, prob, m);
            o = fmaf(pm, __ldg(&tb[m * DD + lane]), o);
        }
        // item = (item + o) @ W.T via smem broadcast
        __syncwarp();
        myIt[lane] = item + o;
        __syncwarp();
        float ni = 0.f;
        #pragma unroll
        for (int e = 0; e < DD; e++) {
            int ee = (e + lane) & (DD - 1);
            ni = fmaf(myIt[ee], sW[lane * DD + ee], ni);
        }
        item = ni;
        __syncwarp();
    }
    out_i[(size_t)p * DD + lane] = item;
}

// ---------------------------------------------------------------------------
extern "C" void kernel_launch(void* const* d_in, const int* in_sizes, int n_in,
                              void* d_out, int out_size) {
    const int*   pos = (const int*)d_in[0];
    const int*   mh  = (const int*)d_in[1];
    const int*   mr  = (const int*)d_in[2];
    const int*   mt  = (const int*)d_in[3];
    const float* uE  = (const float*)d_in[4];
    const float* iE  = (const float*)d_in[5];
    const float* ent = (const float*)d_in[6];
    const float* rel = (const float*)d_in[7];
    const float* W   = (const float*)d_in[8];
    float* out = (float*)d_out;

    const int B    = in_sizes[0];             // 2048
    const int HBM  = in_sizes[1];             // H*B*M = 131072
    const int nhop = HBM / (B * MM);          // 2
    const size_t Ue = (size_t)in_sizes[4];    // USER*D floats
    const size_t Ie = (size_t)in_sizes[5];    // ITEM*D floats

    float* out_u = out;
    float* out_i = out_u + Ue;
    float* out_h = out_i + Ie;
    float* out_t = out_h + (size_t)HBM * DD;
    float* out_r = out_t + (size_t)HBM * DD;

    const int RB  = (HBM + 7) / 8;                      // 16384 r-blocks
    const int HB  = (2 * HBM * 8 + 255) / 256;          // 8192 ht-blocks
    const int Ue4 = (int)(Ue / 4), Ie4 = (int)(Ie / 4);
    const int CB  = (Ue4 + Ie4 + 255) / 256;            // 6250 copy-blocks

    mega_kernel<<<RB + HB + CB, 256>>>(
        mh, mr, mt,
        (const float4*)uE, (const float4*)iE,
        (const float4*)ent, (const float4*)rel,
        (float4*)out_u, (float4*)out_h, (float4*)out_t, (float4*)out_r,
        HBM, RB, HB, Ue4, Ie4);

    ripple_kernel<<<(B + 7) / 8, 256>>>(pos, iE, out_t, W, out_i, B, nhop);
}